// round 13
// baseline (speedup 1.0000x reference)
#include <cuda_runtime.h>
#include <cuda_fp16.h>

#define N_NODES 100000
#define N_EDGES 1600000
#define TOT_E   (N_EDGES + N_NODES)   // edges + self loops
#define F_IN    128
#define HEADS   8
#define HID     8
#define HC      64
#define NCLS    40
#define NEG_SLOPE 0.2f
#define NB_SCAN 98                     // ceil((N_NODES+1)/1024)

typedef unsigned long long u64;

// ---------------- scratch (static device globals, zero-initialized) ---------
__device__ __align__(16) __half2 g_h1h[N_NODES * 32];   // layer1 features, fp16 pairs
__device__ __align__(8) __half2 g_e1[N_NODES * HEADS];  // (exp(as1), exp(.2 as1))
__device__ float g_ad1[N_NODES * HEADS];
__device__ __align__(16) __half2 g_h2h[N_NODES * 20];   // layer2 features, fp16 pairs
__device__ __half2 g_e2[N_NODES];
__device__ float g_ad2[N_NODES];
__device__ int  g_csr_src[TOT_E];
__device__ __align__(8) int g_rank[TOT_E];  // per-edge rank within its destination
__device__ int  g_deg[N_NODES + 1];     // self-cleaning (zeroed in fixup)
__device__ int  g_off[N_NODES + 1];
__device__ int  g_bsum[NB_SCAN];
__device__ int  g_is64;

// ---------------- packed f32x2 helpers ---------------------------------------
__device__ __forceinline__ u64 pack2(float x, float y) {
    u64 r; asm("mov.b64 %0, {%1, %2};" : "=l"(r) : "f"(x), "f"(y)); return r;
}
__device__ __forceinline__ void fma2(u64& a, u64 b, u64 c) {
    asm("fma.rn.f32x2 %0, %1, %2, %0;" : "+l"(a) : "l"(b), "l"(c));
}
__device__ __forceinline__ float2 unpack2(u64 a) {
    float2 f; asm("mov.b64 {%0, %1}, %2;" : "=f"(f.x), "=f"(f.y) : "l"(a)); return f;
}

// ---------------- hist (probe + histogram + rank capture), 2 edges/thread ----
__global__ void hist_dst(const void* __restrict__ ei) {
    __shared__ int s_is64;
    int tid = threadIdx.x;
    if (tid < 32) {
        const long long* p = (const long long*)ei;
        int bad = 0;
#pragma unroll
        for (int k = 0; k < 8; k++) {
            long long v = p[tid * 8 + k];
            if (v < 0 || v >= (long long)N_NODES) bad = 1;
        }
        unsigned m = __ballot_sync(0xffffffffu, bad);
        if (tid == 0) {
            s_is64 = (m == 0u);
            if (blockIdx.x == 0) g_is64 = s_is64;
        }
    }
    __syncthreads();
    unsigned e = (blockIdx.x * 256u + tid) * 2u;
    if (e >= (unsigned)TOT_E) return;
    int d0, d1;
    if (e < (unsigned)N_EDGES) {            // N_EDGES even: pair fully edges
        if (s_is64) {
            longlong2 v = *(const longlong2*)((const long long*)ei + N_EDGES + e);
            d0 = (int)v.x; d1 = (int)v.y;
        } else {
            int2 v = *(const int2*)((const int*)ei + N_EDGES + e);
            d0 = v.x; d1 = v.y;
        }
    } else {
        d0 = (int)(e - (unsigned)N_EDGES);
        d1 = d0 + 1;
    }
    int r0 = atomicAdd(&g_deg[d0], 1);
    int r1 = atomicAdd(&g_deg[d1], 1);
    *(int2*)(g_rank + e) = make_int2(r0, r1);
}

__global__ void __launch_bounds__(1024) scan_blocks() {
    __shared__ int sh[1024];
    int t = threadIdx.x;
    unsigned i = blockIdx.x * 1024u + t;
    int v = (i <= N_NODES) ? g_deg[i] : 0;
    sh[t] = v; __syncthreads();
#pragma unroll
    for (int off = 1; off < 1024; off <<= 1) {
        int add = (t >= off) ? sh[t - off] : 0;
        __syncthreads();
        sh[t] += add;
        __syncthreads();
    }
    if (i <= N_NODES) g_off[i] = sh[t] - v;
    if (t == 1023) g_bsum[blockIdx.x] = sh[t];
}

__global__ void __launch_bounds__(256) fixup_offsets() {
    __shared__ int sb[128];
    int t = threadIdx.x;
    if (t < 128) sb[t] = (t < NB_SCAN) ? g_bsum[t] : 0;
    __syncthreads();
#pragma unroll
    for (int off = 1; off < 128; off <<= 1) {
        int add = (t < 128 && t >= off) ? sb[t - off] : 0;
        __syncthreads();
        if (t < 128) sb[t] += add;
        __syncthreads();
    }
    unsigned i = blockIdx.x * 256u + t;
    if (i > N_NODES) return;
    unsigned b = i >> 10;
    int pre = (b == 0) ? 0 : sb[b - 1];       // exclusive
    g_off[i] = g_off[i] + pre;
    g_deg[i] = 0;                             // self-clean for next call
}

// ---------------- scatter (atomic-free), 2 edges/thread ----------------------
__global__ void scatter_csr(const void* __restrict__ ei) {
    unsigned e = (blockIdx.x * 256u + threadIdx.x) * 2u;
    if (e >= (unsigned)TOT_E) return;
    int s0, s1, d0, d1;
    if (e < (unsigned)N_EDGES) {
        if (g_is64) {
            longlong2 vs = *(const longlong2*)((const long long*)ei + e);
            longlong2 vd = *(const longlong2*)((const long long*)ei + N_EDGES + e);
            s0 = (int)vs.x; s1 = (int)vs.y; d0 = (int)vd.x; d1 = (int)vd.y;
        } else {
            int2 vs = *(const int2*)((const int*)ei + e);
            int2 vd = *(const int2*)((const int*)ei + N_EDGES + e);
            s0 = vs.x; s1 = vs.y; d0 = vd.x; d1 = vd.y;
        }
    } else {
        s0 = d0 = (int)(e - (unsigned)N_EDGES);
        s1 = d1 = s0 + 1;
    }
    int2 r = *(const int2*)(g_rank + e);
    g_csr_src[g_off[d0] + r.x] = s0;
    g_csr_src[g_off[d1] + r.y] = s1;
}

// ---------------- layer 1 GEMM: 8 nodes/warp, f32x2 accumulation -------------
__global__ void __launch_bounds__(256) gemm1(const float* __restrict__ x,
                                             const float* __restrict__ W,
                                             const float* __restrict__ asrc,
                                             const float* __restrict__ adst) {
    __shared__ float Ws[F_IN * HC];           // 32 KB
    __shared__ float xs[8][F_IN * 8];         // 32 KB: [warp][k*8 + node]
    __shared__ float as_s[HC], ad_s[HC];

    int tid = threadIdx.x;
    for (int i = tid; i < F_IN * HC; i += 256) Ws[i] = W[i];
    if (tid < HC) { as_s[tid] = asrc[tid]; ad_s[tid] = adst[tid]; }

    int warp = tid >> 5, lane = tid & 31;
    int n0 = blockIdx.x * 64 + warp * 8;

#pragma unroll
    for (int u = 0; u < 8; u++) {
        int n = n0 + u; if (n >= N_NODES) n = N_NODES - 1;
        const float* xr = x + (size_t)n * F_IN;
#pragma unroll
        for (int c = 0; c < 4; c++) {
            int k = lane + c * 32;
            xs[warp][k * 8 + u] = xr[k];
        }
    }
    __syncthreads();

    const float2* W2p = (const float2*)Ws;
    u64 acc[8];
#pragma unroll
    for (int u = 0; u < 8; u++) acc[u] = 0;

#pragma unroll 4
    for (int k = 0; k < F_IN; k++) {
        float4 xa = *(const float4*)&xs[warp][k * 8];
        float4 xb = *(const float4*)&xs[warp][k * 8 + 4];
        float2 wv = W2p[k * 32 + lane];
        u64 wp = pack2(wv.x, wv.y);
        fma2(acc[0], pack2(xa.x, xa.x), wp);
        fma2(acc[1], pack2(xa.y, xa.y), wp);
        fma2(acc[2], pack2(xa.z, xa.z), wp);
        fma2(acc[3], pack2(xa.w, xa.w), wp);
        fma2(acc[4], pack2(xb.x, xb.x), wp);
        fma2(acc[5], pack2(xb.y, xb.y), wp);
        fma2(acc[6], pack2(xb.z, xb.z), wp);
        fma2(acc[7], pack2(xb.w, xb.w), wp);
    }

    int j0 = lane * 2;
    float asx = as_s[j0], asy = as_s[j0 + 1];
    float adx = ad_s[j0], ady = ad_s[j0 + 1];

#pragma unroll
    for (int u = 0; u < 8; u++) {
        int n = n0 + u;
        float2 f = unpack2(acc[u]);
        float A0 = f.x, A1 = f.y;
        float ps = A0 * asx + A1 * asy;
        float pd = A0 * adx + A1 * ady;
        ps += __shfl_xor_sync(0xffffffffu, ps, 1);
        ps += __shfl_xor_sync(0xffffffffu, ps, 2);
        pd += __shfl_xor_sync(0xffffffffu, pd, 1);
        pd += __shfl_xor_sync(0xffffffffu, pd, 2);
        if (n < N_NODES) {
            g_h1h[n * 32 + lane] = __floats2half2_rn(A0, A1);
            if ((lane & 3) == 0) {
                int hh = lane >> 2;
                g_e1[n * HEADS + hh] = __floats2half2_rn(__expf(ps), __expf(0.2f * ps));
                g_ad1[n * HEADS + hh] = pd;
            }
        }
    }
}

// ---------------- layer 1 aggregation + fused gemm2 --------------------------
// Warp per node. Lane = slot p=lane>>3 x head q=lane&7. Direct csr loads,
// FFMA2 packed accumulation, unrolled fused-gemm2 epilogue.
__global__ void __launch_bounds__(256) edge1_fused(const float* __restrict__ b1,
                                                   const float* __restrict__ W2,
                                                   const float* __restrict__ as2v,
                                                   const float* __restrict__ ad2v) {
    __shared__ float Ws2[HC * NCLS];          // 10 KB
    __shared__ float a2s[NCLS], a2d[NCLS];
    __shared__ __align__(16) float hs[8][HC];

    int tid = threadIdx.x;
    for (int i = tid; i < HC * NCLS; i += 256) Ws2[i] = W2[i];
    if (tid < NCLS) { a2s[tid] = as2v[tid]; a2d[tid] = ad2v[tid]; }
    __syncthreads();

    int warp = tid >> 5, lane = tid & 31;
    int n = blockIdx.x * 8 + warp;
    if (n >= N_NODES) return;
    int q = lane & 7;                          // head
    int p = lane >> 3;                         // edge slot 0..3

    float ad  = g_ad1[n * 8 + q];
    float epd = __expf(ad);
    float emd = __expf(0.2f * ad);
    float den = 0.f;
    u64 A01 = 0, A23 = 0, A45 = 0, A67 = 0;

#define EDGE1(S)                                                                 \
    {                                                                            \
        __half2 es = g_e1[(S) * 8 + q];                                          \
        uint4 h = *(const uint4*)(g_h1h + (S) * 32 + q * 4);                     \
        float2 ef = __half22float2(es);                                          \
        float pe = ef.x * epd;                                                   \
        float e = pe > 1.f ? pe : ef.y * emd;                                    \
        den += e;                                                                \
        u64 eS = pack2(e, e);                                                    \
        float2 v0 = __half22float2(*(__half2*)&h.x);                             \
        float2 v1 = __half22float2(*(__half2*)&h.y);                             \
        float2 v2 = __half22float2(*(__half2*)&h.z);                             \
        float2 v3 = __half22float2(*(__half2*)&h.w);                             \
        fma2(A01, pack2(v0.x, v0.y), eS);                                        \
        fma2(A23, pack2(v1.x, v1.y), eS);                                        \
        fma2(A45, pack2(v2.x, v2.y), eS);                                        \
        fma2(A67, pack2(v3.x, v3.y), eS);                                        \
    }

    int k = g_off[n] + p;
    int end = g_off[n + 1];
    for (; k + 12 < end; k += 16) {           // 4 edges per lane per iter
        int s0 = g_csr_src[k];
        int s1 = g_csr_src[k + 4];
        int s2 = g_csr_src[k + 8];
        int s3 = g_csr_src[k + 12];
        EDGE1(s0) EDGE1(s1) EDGE1(s2) EDGE1(s3)
    }
    for (; k < end; k += 4) {
        int s = g_csr_src[k];
        EDGE1(s)
    }
#undef EDGE1

    float2 f01 = unpack2(A01), f23 = unpack2(A23), f45 = unpack2(A45), f67 = unpack2(A67);
    float a0 = f01.x, a1 = f01.y, a2 = f23.x, a3 = f23.y,
          a4 = f45.x, a5 = f45.y, a6 = f67.x, a7 = f67.y;

#define RED(X) X += __shfl_xor_sync(0xffffffffu, X, 8); X += __shfl_xor_sync(0xffffffffu, X, 16);
    RED(den) RED(a0) RED(a1) RED(a2) RED(a3) RED(a4) RED(a5) RED(a6) RED(a7)
#undef RED

    if (p == 0) {
        int c0 = q * 8;
        float4 ba = *(const float4*)(b1 + c0);
        float4 bb = *(const float4*)(b1 + c0 + 4);
        float inv = 1.f / (den + 1e-16f);
        hs[warp][c0]     = fmaxf(a0 * inv + ba.x, 0.f);
        hs[warp][c0 + 1] = fmaxf(a1 * inv + ba.y, 0.f);
        hs[warp][c0 + 2] = fmaxf(a2 * inv + ba.z, 0.f);
        hs[warp][c0 + 3] = fmaxf(a3 * inv + ba.w, 0.f);
        hs[warp][c0 + 4] = fmaxf(a4 * inv + bb.x, 0.f);
        hs[warp][c0 + 5] = fmaxf(a5 * inv + bb.y, 0.f);
        hs[warp][c0 + 6] = fmaxf(a6 * inv + bb.z, 0.f);
        hs[warp][c0 + 7] = fmaxf(a7 * inv + bb.w, 0.f);
    }
    __syncwarp();

    // ---- fused layer-2 GEMM: float4 hs broadcast, width-4 unrolled ----
    float acc0 = 0.f, acc1 = 0.f;
    int l8 = 32 + (lane & 7);
#pragma unroll
    for (int w = 0; w < HC; w += 4) {
        float4 hv = *(const float4*)&hs[warp][w];
        acc0 += hv.x * Ws2[(w + 0) * NCLS + lane] + hv.y * Ws2[(w + 1) * NCLS + lane]
              + hv.z * Ws2[(w + 2) * NCLS + lane] + hv.w * Ws2[(w + 3) * NCLS + lane];
        acc1 += hv.x * Ws2[(w + 0) * NCLS + l8] + hv.y * Ws2[(w + 1) * NCLS + l8]
              + hv.z * Ws2[(w + 2) * NCLS + l8] + hv.w * Ws2[(w + 3) * NCLS + l8];
    }

    __half* h2p = (__half*)g_h2h;
    h2p[n * NCLS + lane] = __float2half_rn(acc0);
    if (lane < 8) h2p[n * NCLS + 32 + lane] = __float2half_rn(acc1);

    float ps = acc0 * a2s[lane] + (lane < 8 ? acc1 * a2s[32 + lane] : 0.f);
    float pd = acc0 * a2d[lane] + (lane < 8 ? acc1 * a2d[32 + lane] : 0.f);
#pragma unroll
    for (int o = 16; o; o >>= 1) {
        ps += __shfl_xor_sync(0xffffffffu, ps, o);
        pd += __shfl_xor_sync(0xffffffffu, pd, o);
    }
    if (lane == 0) {
        g_e2[n] = __floats2half2_rn(__expf(ps), __expf(0.2f * ps));
        g_ad2[n] = pd;
    }
}

// ---------------- layer 2 CSR aggregation ------------------------------------
// 6 groups of 5 lanes; lane t owns classes [8t,8t+8). FFMA2 accumulation.
__global__ void __launch_bounds__(256) edge_csr2(float* __restrict__ out,
                                                 const float* __restrict__ b2) {
    int warp = (blockIdx.x * 256 + threadIdx.x) >> 5;
    int lane = threadIdx.x & 31;
    if (warp >= N_NODES) return;
    int n = warp;
    int g = lane / 5;
    int t = lane - g * 5;
    bool live = g < 6;
    int ti = live ? t : 0;

    float ad  = g_ad2[n];
    float epd = __expf(ad);
    float emd = __expf(0.2f * ad);
    float den = 0.f;
    u64 A01 = 0, A23 = 0, A45 = 0, A67 = 0;

#define EDGE2(S)                                                                 \
    {                                                                            \
        __half2 es = g_e2[(S)];                                                  \
        uint4 h = *(const uint4*)((const uint4*)g_h2h + (S) * 5 + ti);           \
        float2 ef = __half22float2(es);                                          \
        float pe = ef.x * epd;                                                   \
        float e = pe > 1.f ? pe : ef.y * emd;                                    \
        den += e;                                                                \
        u64 eS = pack2(e, e);                                                    \
        float2 v0 = __half22float2(*(__half2*)&h.x);                             \
        float2 v1 = __half22float2(*(__half2*)&h.y);                             \
        float2 v2 = __half22float2(*(__half2*)&h.z);                             \
        float2 v3 = __half22float2(*(__half2*)&h.w);                             \
        fma2(A01, pack2(v0.x, v0.y), eS);                                        \
        fma2(A23, pack2(v1.x, v1.y), eS);                                        \
        fma2(A45, pack2(v2.x, v2.y), eS);                                        \
        fma2(A67, pack2(v3.x, v3.y), eS);                                        \
    }

    int k = g_off[n] + g;
    int end = live ? g_off[n + 1] : 0;
    if (!live) k = 0;
    for (; k + 6 < end; k += 12) {            // 2 edges per group per iter
        int s0 = g_csr_src[k];
        int s1 = g_csr_src[k + 6];
        EDGE2(s0) EDGE2(s1)
    }
    for (; k < end; k += 6) {
        int s = g_csr_src[k];
        EDGE2(s)
    }
#undef EDGE2

    float2 f01 = unpack2(A01), f23 = unpack2(A23), f45 = unpack2(A45), f67 = unpack2(A67);
    float a0 = f01.x, a1 = f01.y, a2 = f23.x, a3 = f23.y,
          a4 = f45.x, a5 = f45.y, a6 = f67.x, a7 = f67.y;

#define RED(X)                                                                   \
    {                                                                            \
        float w = __shfl_sync(0xffffffffu, X, (lane + 15) & 31); X += w;         \
        float u = __shfl_sync(0xffffffffu, X, (lane + 5) & 31);                  \
        float v = __shfl_sync(0xffffffffu, X, (lane + 10) & 31);                 \
        X += u + v;                                                              \
    }
    RED(den) RED(a0) RED(a1) RED(a2) RED(a3) RED(a4) RED(a5) RED(a6) RED(a7)
#undef RED

    if (lane < 5) {
        int c0 = lane * 8;
        float4 ba = *(const float4*)(b2 + c0);
        float4 bb = *(const float4*)(b2 + c0 + 4);
        float inv = 1.f / (den + 1e-16f);
        float4 r0, r1;
        r0.x = a0 * inv + ba.x; r0.y = a1 * inv + ba.y;
        r0.z = a2 * inv + ba.z; r0.w = a3 * inv + ba.w;
        r1.x = a4 * inv + bb.x; r1.y = a5 * inv + bb.y;
        r1.z = a6 * inv + bb.z; r1.w = a7 * inv + bb.w;
        *(float4*)(out + n * NCLS + c0)     = r0;
        *(float4*)(out + n * NCLS + c0 + 4) = r1;
    }
}

// ---------------- launch -----------------------------------------------------
extern "C" void kernel_launch(void* const* d_in, const int* in_sizes, int n_in,
                              void* d_out, int out_size) {
    const float* x   = (const float*)d_in[0];
    const void*  ei  = d_in[1];
    const float* W1  = (const float*)d_in[2];
    const float* as1 = (const float*)d_in[3];
    const float* ad1 = (const float*)d_in[4];
    const float* b1  = (const float*)d_in[5];
    const float* W2  = (const float*)d_in[6];
    const float* as2 = (const float*)d_in[7];
    const float* ad2 = (const float*)d_in[8];
    const float* b2  = (const float*)d_in[9];
    float*       out = (float*)d_out;

    // fork: CSR build on side stream, gemm1 concurrently on main stream
    cudaStream_t s1;
    cudaStreamCreateWithFlags(&s1, cudaStreamNonBlocking);
    cudaEvent_t ev0, ev1;
    cudaEventCreateWithFlags(&ev0, cudaEventDisableTiming);
    cudaEventCreateWithFlags(&ev1, cudaEventDisableTiming);

    cudaEventRecord(ev0, 0);
    cudaStreamWaitEvent(s1, ev0, 0);

    // ---- CSR build (side stream) ----
    hist_dst<<<((unsigned)TOT_E / 2 + 255) / 256, 256, 0, s1>>>(ei);
    scan_blocks<<<NB_SCAN, 1024, 0, s1>>>();
    fixup_offsets<<<(N_NODES + 256) / 256, 256, 0, s1>>>();
    scatter_csr<<<((unsigned)TOT_E / 2 + 255) / 256, 256, 0, s1>>>(ei);
    cudaEventRecord(ev1, s1);

    // ---- layer 1 GEMM (main stream, overlapped) ----
    gemm1<<<(N_NODES + 63) / 64, 256>>>(x, W1, as1, ad1);

    // join
    cudaStreamWaitEvent(0, ev1, 0);

    // ---- layer 1 aggregation + fused layer-2 GEMM ----
    edge1_fused<<<(N_NODES + 7) / 8, 256>>>(b1, W2, as2, ad2);

    // ---- layer 2 ----
    edge_csr2<<<(N_NODES * 32 + 255) / 256, 256>>>(out, b2);

    cudaEventDestroy(ev0);
    cudaEventDestroy(ev1);
    cudaStreamDestroy(s1);
}

// round 14
// speedup vs baseline: 1.0750x; 1.0750x over previous
#include <cuda_runtime.h>
#include <cuda_fp16.h>

#define N_NODES 100000
#define N_EDGES 1600000
#define TOT_E   (N_EDGES + N_NODES)   // edges + self loops
#define F_IN    128
#define HEADS   8
#define HID     8
#define HC      64
#define NCLS    40
#define NEG_SLOPE 0.2f
#define NB_SCAN 98                     // ceil((N_NODES+1)/1024)

typedef unsigned long long u64;

// ---------------- scratch (static device globals, zero-initialized) ---------
__device__ __align__(16) __half2 g_h1h[N_NODES * 32];   // layer1 features, fp16 pairs
__device__ __align__(8) __half2 g_e1[N_NODES * HEADS];  // (exp(as1), exp(.2 as1))
__device__ float g_ad1[N_NODES * HEADS];
__device__ __align__(16) __half2 g_h2h[N_NODES * 20];   // layer2 features, fp16 pairs
__device__ __half2 g_e2[N_NODES];
__device__ float g_ad2[N_NODES];
__device__ int  g_csr_src[TOT_E];
__device__ __align__(8) int g_rank[TOT_E];  // per-edge rank within its destination
__device__ int  g_deg[N_NODES + 1];     // self-cleaning (zeroed in fixup)
__device__ int  g_off[N_NODES + 1];
__device__ int  g_bsum[NB_SCAN];
__device__ int  g_is64;

// ---------------- packed f32x2 helpers (gemm1 only) --------------------------
__device__ __forceinline__ u64 pack2(float x, float y) {
    u64 r; asm("mov.b64 %0, {%1, %2};" : "=l"(r) : "f"(x), "f"(y)); return r;
}
__device__ __forceinline__ void fma2(u64& a, u64 b, u64 c) {
    asm("fma.rn.f32x2 %0, %1, %2, %0;" : "+l"(a) : "l"(b), "l"(c));
}
__device__ __forceinline__ float2 unpack2(u64 a) {
    float2 f; asm("mov.b64 {%0, %1}, %2;" : "=f"(f.x), "=f"(f.y) : "l"(a)); return f;
}

// ---------------- hist (probe + histogram + rank capture), 2 edges/thread ----
__global__ void hist_dst(const void* __restrict__ ei) {
    __shared__ int s_is64;
    int tid = threadIdx.x;
    if (tid < 32) {
        const long long* p = (const long long*)ei;
        int bad = 0;
#pragma unroll
        for (int k = 0; k < 8; k++) {
            long long v = p[tid * 8 + k];
            if (v < 0 || v >= (long long)N_NODES) bad = 1;
        }
        unsigned m = __ballot_sync(0xffffffffu, bad);
        if (tid == 0) {
            s_is64 = (m == 0u);
            if (blockIdx.x == 0) g_is64 = s_is64;
        }
    }
    __syncthreads();
    unsigned e = (blockIdx.x * 256u + tid) * 2u;
    if (e >= (unsigned)TOT_E) return;
    int d0, d1;
    if (e < (unsigned)N_EDGES) {            // N_EDGES even: pair fully edges
        if (s_is64) {
            longlong2 v = *(const longlong2*)((const long long*)ei + N_EDGES + e);
            d0 = (int)v.x; d1 = (int)v.y;
        } else {
            int2 v = *(const int2*)((const int*)ei + N_EDGES + e);
            d0 = v.x; d1 = v.y;
        }
    } else {
        d0 = (int)(e - (unsigned)N_EDGES);
        d1 = d0 + 1;
    }
    int r0 = atomicAdd(&g_deg[d0], 1);
    int r1 = atomicAdd(&g_deg[d1], 1);
    *(int2*)(g_rank + e) = make_int2(r0, r1);
}

__global__ void __launch_bounds__(1024) scan_blocks() {
    __shared__ int sh[1024];
    int t = threadIdx.x;
    unsigned i = blockIdx.x * 1024u + t;
    int v = (i <= N_NODES) ? g_deg[i] : 0;
    sh[t] = v; __syncthreads();
#pragma unroll
    for (int off = 1; off < 1024; off <<= 1) {
        int add = (t >= off) ? sh[t - off] : 0;
        __syncthreads();
        sh[t] += add;
        __syncthreads();
    }
    if (i <= N_NODES) g_off[i] = sh[t] - v;
    if (t == 1023) g_bsum[blockIdx.x] = sh[t];
}

__global__ void __launch_bounds__(256) fixup_offsets() {
    __shared__ int sb[128];
    int t = threadIdx.x;
    if (t < 128) sb[t] = (t < NB_SCAN) ? g_bsum[t] : 0;
    __syncthreads();
#pragma unroll
    for (int off = 1; off < 128; off <<= 1) {
        int add = (t < 128 && t >= off) ? sb[t - off] : 0;
        __syncthreads();
        if (t < 128) sb[t] += add;
        __syncthreads();
    }
    unsigned i = blockIdx.x * 256u + t;
    if (i > N_NODES) return;
    unsigned b = i >> 10;
    int pre = (b == 0) ? 0 : sb[b - 1];       // exclusive
    g_off[i] = g_off[i] + pre;
    g_deg[i] = 0;                             // self-clean for next call
}

// ---------------- scatter (atomic-free), 2 edges/thread ----------------------
__global__ void scatter_csr(const void* __restrict__ ei) {
    unsigned e = (blockIdx.x * 256u + threadIdx.x) * 2u;
    if (e >= (unsigned)TOT_E) return;
    int s0, s1, d0, d1;
    if (e < (unsigned)N_EDGES) {
        if (g_is64) {
            longlong2 vs = *(const longlong2*)((const long long*)ei + e);
            longlong2 vd = *(const longlong2*)((const long long*)ei + N_EDGES + e);
            s0 = (int)vs.x; s1 = (int)vs.y; d0 = (int)vd.x; d1 = (int)vd.y;
        } else {
            int2 vs = *(const int2*)((const int*)ei + e);
            int2 vd = *(const int2*)((const int*)ei + N_EDGES + e);
            s0 = vs.x; s1 = vs.y; d0 = vd.x; d1 = vd.y;
        }
    } else {
        s0 = d0 = (int)(e - (unsigned)N_EDGES);
        s1 = d1 = s0 + 1;
    }
    int2 r = *(const int2*)(g_rank + e);
    g_csr_src[g_off[d0] + r.x] = s0;
    g_csr_src[g_off[d1] + r.y] = s1;
}

// ---------------- layer 1 GEMM: 8 nodes/warp, f32x2 accumulation -------------
__global__ void __launch_bounds__(256) gemm1(const float* __restrict__ x,
                                             const float* __restrict__ W,
                                             const float* __restrict__ asrc,
                                             const float* __restrict__ adst) {
    __shared__ float Ws[F_IN * HC];           // 32 KB
    __shared__ float xs[8][F_IN * 8];         // 32 KB: [warp][k*8 + node]
    __shared__ float as_s[HC], ad_s[HC];

    int tid = threadIdx.x;
    for (int i = tid; i < F_IN * HC; i += 256) Ws[i] = W[i];
    if (tid < HC) { as_s[tid] = asrc[tid]; ad_s[tid] = adst[tid]; }

    int warp = tid >> 5, lane = tid & 31;
    int n0 = blockIdx.x * 64 + warp * 8;

#pragma unroll
    for (int u = 0; u < 8; u++) {
        int n = n0 + u; if (n >= N_NODES) n = N_NODES - 1;
        const float* xr = x + (size_t)n * F_IN;
#pragma unroll
        for (int c = 0; c < 4; c++) {
            int k = lane + c * 32;
            xs[warp][k * 8 + u] = xr[k];
        }
    }
    __syncthreads();

    const float2* W2p = (const float2*)Ws;
    u64 acc[8];
#pragma unroll
    for (int u = 0; u < 8; u++) acc[u] = 0;

#pragma unroll 4
    for (int k = 0; k < F_IN; k++) {
        float4 xa = *(const float4*)&xs[warp][k * 8];
        float4 xb = *(const float4*)&xs[warp][k * 8 + 4];
        float2 wv = W2p[k * 32 + lane];
        u64 wp = pack2(wv.x, wv.y);
        fma2(acc[0], pack2(xa.x, xa.x), wp);
        fma2(acc[1], pack2(xa.y, xa.y), wp);
        fma2(acc[2], pack2(xa.z, xa.z), wp);
        fma2(acc[3], pack2(xa.w, xa.w), wp);
        fma2(acc[4], pack2(xb.x, xb.x), wp);
        fma2(acc[5], pack2(xb.y, xb.y), wp);
        fma2(acc[6], pack2(xb.z, xb.z), wp);
        fma2(acc[7], pack2(xb.w, xb.w), wp);
    }

    int j0 = lane * 2;
    float asx = as_s[j0], asy = as_s[j0 + 1];
    float adx = ad_s[j0], ady = ad_s[j0 + 1];

#pragma unroll
    for (int u = 0; u < 8; u++) {
        int n = n0 + u;
        float2 f = unpack2(acc[u]);
        float A0 = f.x, A1 = f.y;
        float ps = A0 * asx + A1 * asy;
        float pd = A0 * adx + A1 * ady;
        ps += __shfl_xor_sync(0xffffffffu, ps, 1);
        ps += __shfl_xor_sync(0xffffffffu, ps, 2);
        pd += __shfl_xor_sync(0xffffffffu, pd, 1);
        pd += __shfl_xor_sync(0xffffffffu, pd, 2);
        if (n < N_NODES) {
            g_h1h[n * 32 + lane] = __floats2half2_rn(A0, A1);
            if ((lane & 3) == 0) {
                int hh = lane >> 2;
                g_e1[n * HEADS + hh] = __floats2half2_rn(__expf(ps), __expf(0.2f * ps));
                g_ad1[n * HEADS + hh] = pd;
            }
        }
    }
}

// ---------------- layer 1 aggregation (direct csr loads) + fused gemm2 ------
// Warp per node. Lane = slot p=lane>>3 x head q=lane&7. Scalar FMA accums
// (FFMA2 regression in R13 — reverted). Unroll 4.
__global__ void __launch_bounds__(256) edge1_fused(const float* __restrict__ b1,
                                                   const float* __restrict__ W2,
                                                   const float* __restrict__ as2v,
                                                   const float* __restrict__ ad2v) {
    __shared__ float Ws2[HC * NCLS];          // 10 KB
    __shared__ float a2s[NCLS], a2d[NCLS];
    __shared__ __align__(16) float hs[8][HC];

    int tid = threadIdx.x;
    for (int i = tid; i < HC * NCLS; i += 256) Ws2[i] = W2[i];
    if (tid < NCLS) { a2s[tid] = as2v[tid]; a2d[tid] = ad2v[tid]; }
    __syncthreads();

    int warp = tid >> 5, lane = tid & 31;
    int n = blockIdx.x * 8 + warp;
    if (n >= N_NODES) return;
    int q = lane & 7;                          // head
    int p = lane >> 3;                         // edge slot 0..3

    float ad  = g_ad1[n * 8 + q];
    float epd = __expf(ad);
    float emd = __expf(0.2f * ad);
    float den = 0.f;
    float a0 = 0.f, a1 = 0.f, a2 = 0.f, a3 = 0.f,
          a4 = 0.f, a5 = 0.f, a6 = 0.f, a7 = 0.f;

#define ACCUM(E, H)                                                              \
    {                                                                            \
        float2 v0 = __half22float2(*(__half2*)&(H).x);                           \
        float2 v1 = __half22float2(*(__half2*)&(H).y);                           \
        float2 v2 = __half22float2(*(__half2*)&(H).z);                           \
        float2 v3 = __half22float2(*(__half2*)&(H).w);                           \
        a0 += (E) * v0.x; a1 += (E) * v0.y; a2 += (E) * v1.x; a3 += (E) * v1.y;  \
        a4 += (E) * v2.x; a5 += (E) * v2.y; a6 += (E) * v3.x; a7 += (E) * v3.y;  \
    }
#define EDGE1(S)                                                                 \
    {                                                                            \
        __half2 es = g_e1[(S) * 8 + q];                                          \
        uint4 h = *(const uint4*)(g_h1h + (S) * 32 + q * 4);                     \
        float2 ef = __half22float2(es);                                          \
        float pe = ef.x * epd;                                                   \
        float e = pe > 1.f ? pe : ef.y * emd;                                    \
        den += e;                                                                \
        ACCUM(e, h)                                                              \
    }

    int k = g_off[n] + p;
    int end = g_off[n + 1];
    for (; k + 12 < end; k += 16) {           // 4 edges per lane per iter
        int s0 = g_csr_src[k];
        int s1 = g_csr_src[k + 4];
        int s2 = g_csr_src[k + 8];
        int s3 = g_csr_src[k + 12];
        EDGE1(s0) EDGE1(s1) EDGE1(s2) EDGE1(s3)
    }
    for (; k < end; k += 4) {
        int s = g_csr_src[k];
        EDGE1(s)
    }
#undef EDGE1
#undef ACCUM

#define RED(X) X += __shfl_xor_sync(0xffffffffu, X, 8); X += __shfl_xor_sync(0xffffffffu, X, 16);
    RED(den) RED(a0) RED(a1) RED(a2) RED(a3) RED(a4) RED(a5) RED(a6) RED(a7)
#undef RED

    if (p == 0) {
        int c0 = q * 8;
        float4 ba = *(const float4*)(b1 + c0);
        float4 bb = *(const float4*)(b1 + c0 + 4);
        float inv = 1.f / (den + 1e-16f);
        hs[warp][c0]     = fmaxf(a0 * inv + ba.x, 0.f);
        hs[warp][c0 + 1] = fmaxf(a1 * inv + ba.y, 0.f);
        hs[warp][c0 + 2] = fmaxf(a2 * inv + ba.z, 0.f);
        hs[warp][c0 + 3] = fmaxf(a3 * inv + ba.w, 0.f);
        hs[warp][c0 + 4] = fmaxf(a4 * inv + bb.x, 0.f);
        hs[warp][c0 + 5] = fmaxf(a5 * inv + bb.y, 0.f);
        hs[warp][c0 + 6] = fmaxf(a6 * inv + bb.z, 0.f);
        hs[warp][c0 + 7] = fmaxf(a7 * inv + bb.w, 0.f);
    }
    __syncwarp();

    // ---- fused layer-2 GEMM: float4 hs broadcast, width-4 unrolled ----
    float acc0 = 0.f, acc1 = 0.f;
    int l8 = 32 + (lane & 7);
#pragma unroll
    for (int w = 0; w < HC; w += 4) {
        float4 hv = *(const float4*)&hs[warp][w];
        acc0 += hv.x * Ws2[(w + 0) * NCLS + lane] + hv.y * Ws2[(w + 1) * NCLS + lane]
              + hv.z * Ws2[(w + 2) * NCLS + lane] + hv.w * Ws2[(w + 3) * NCLS + lane];
        acc1 += hv.x * Ws2[(w + 0) * NCLS + l8] + hv.y * Ws2[(w + 1) * NCLS + l8]
              + hv.z * Ws2[(w + 2) * NCLS + l8] + hv.w * Ws2[(w + 3) * NCLS + l8];
    }

    __half* h2p = (__half*)g_h2h;
    h2p[n * NCLS + lane] = __float2half_rn(acc0);
    if (lane < 8) h2p[n * NCLS + 32 + lane] = __float2half_rn(acc1);

    float ps = acc0 * a2s[lane] + (lane < 8 ? acc1 * a2s[32 + lane] : 0.f);
    float pd = acc0 * a2d[lane] + (lane < 8 ? acc1 * a2d[32 + lane] : 0.f);
#pragma unroll
    for (int o = 16; o; o >>= 1) {
        ps += __shfl_xor_sync(0xffffffffu, ps, o);
        pd += __shfl_xor_sync(0xffffffffu, pd, o);
    }
    if (lane == 0) {
        g_e2[n] = __floats2half2_rn(__expf(ps), __expf(0.2f * ps));
        g_ad2[n] = pd;
    }
}

// ---------------- layer 2 CSR aggregation (direct csr loads) -----------------
// 6 groups of 5 lanes; lane t owns classes [8t,8t+8). Scalar FMA accums.
__global__ void __launch_bounds__(256) edge_csr2(float* __restrict__ out,
                                                 const float* __restrict__ b2) {
    int warp = (blockIdx.x * 256 + threadIdx.x) >> 5;
    int lane = threadIdx.x & 31;
    if (warp >= N_NODES) return;
    int n = warp;
    int g = lane / 5;
    int t = lane - g * 5;
    bool live = g < 6;
    int ti = live ? t : 0;

    float ad  = g_ad2[n];
    float epd = __expf(ad);
    float emd = __expf(0.2f * ad);
    float den = 0.f;
    float a0 = 0.f, a1 = 0.f, a2 = 0.f, a3 = 0.f,
          a4 = 0.f, a5 = 0.f, a6 = 0.f, a7 = 0.f;

#define ACCUM(E, H)                                                              \
    {                                                                            \
        float2 v0 = __half22float2(*(__half2*)&(H).x);                           \
        float2 v1 = __half22float2(*(__half2*)&(H).y);                           \
        float2 v2 = __half22float2(*(__half2*)&(H).z);                           \
        float2 v3 = __half22float2(*(__half2*)&(H).w);                           \
        a0 += (E) * v0.x; a1 += (E) * v0.y; a2 += (E) * v1.x; a3 += (E) * v1.y;  \
        a4 += (E) * v2.x; a5 += (E) * v2.y; a6 += (E) * v3.x; a7 += (E) * v3.y;  \
    }
#define EDGE2(S)                                                                 \
    {                                                                            \
        __half2 es = g_e2[(S)];                                                  \
        uint4 h = *(const uint4*)((const uint4*)g_h2h + (S) * 5 + ti);           \
        float2 ef = __half22float2(es);                                          \
        float pe = ef.x * epd;                                                   \
        float e = pe > 1.f ? pe : ef.y * emd;                                    \
        den += e;                                                                \
        ACCUM(e, h)                                                              \
    }

    int k = g_off[n] + g;
    int end = live ? g_off[n + 1] : 0;
    if (!live) k = 0;
    for (; k + 6 < end; k += 12) {            // 2 edges per group per iter
        int s0 = g_csr_src[k];
        int s1 = g_csr_src[k + 6];
        EDGE2(s0) EDGE2(s1)
    }
    for (; k < end; k += 6) {
        int s = g_csr_src[k];
        EDGE2(s)
    }
#undef EDGE2
#undef ACCUM

#define RED(X)                                                                   \
    {                                                                            \
        float w = __shfl_sync(0xffffffffu, X, (lane + 15) & 31); X += w;         \
        float u = __shfl_sync(0xffffffffu, X, (lane + 5) & 31);                  \
        float v = __shfl_sync(0xffffffffu, X, (lane + 10) & 31);                 \
        X += u + v;                                                              \
    }
    RED(den) RED(a0) RED(a1) RED(a2) RED(a3) RED(a4) RED(a5) RED(a6) RED(a7)
#undef RED

    if (lane < 5) {
        int c0 = lane * 8;
        float4 ba = *(const float4*)(b2 + c0);
        float4 bb = *(const float4*)(b2 + c0 + 4);
        float inv = 1.f / (den + 1e-16f);
        float4 r0, r1;
        r0.x = a0 * inv + ba.x; r0.y = a1 * inv + ba.y;
        r0.z = a2 * inv + ba.z; r0.w = a3 * inv + ba.w;
        r1.x = a4 * inv + bb.x; r1.y = a5 * inv + bb.y;
        r1.z = a6 * inv + bb.z; r1.w = a7 * inv + bb.w;
        *(float4*)(out + n * NCLS + c0)     = r0;
        *(float4*)(out + n * NCLS + c0 + 4) = r1;
    }
}

// ---------------- launch -----------------------------------------------------
extern "C" void kernel_launch(void* const* d_in, const int* in_sizes, int n_in,
                              void* d_out, int out_size) {
    const float* x   = (const float*)d_in[0];
    const void*  ei  = d_in[1];
    const float* W1  = (const float*)d_in[2];
    const float* as1 = (const float*)d_in[3];
    const float* ad1 = (const float*)d_in[4];
    const float* b1  = (const float*)d_in[5];
    const float* W2  = (const float*)d_in[6];
    const float* as2 = (const float*)d_in[7];
    const float* ad2 = (const float*)d_in[8];
    const float* b2  = (const float*)d_in[9];
    float*       out = (float*)d_out;

    // fork: CSR build on side stream, gemm1 concurrently on main stream
    cudaStream_t s1;
    cudaStreamCreateWithFlags(&s1, cudaStreamNonBlocking);
    cudaEvent_t ev0, ev1;
    cudaEventCreateWithFlags(&ev0, cudaEventDisableTiming);
    cudaEventCreateWithFlags(&ev1, cudaEventDisableTiming);

    cudaEventRecord(ev0, 0);
    cudaStreamWaitEvent(s1, ev0, 0);

    // ---- CSR build (side stream) ----
    hist_dst<<<((unsigned)TOT_E / 2 + 255) / 256, 256, 0, s1>>>(ei);
    scan_blocks<<<NB_SCAN, 1024, 0, s1>>>();
    fixup_offsets<<<(N_NODES + 256) / 256, 256, 0, s1>>>();
    scatter_csr<<<((unsigned)TOT_E / 2 + 255) / 256, 256, 0, s1>>>(ei);
    cudaEventRecord(ev1, s1);

    // ---- layer 1 GEMM (main stream, overlapped) ----
    gemm1<<<(N_NODES + 63) / 64, 256>>>(x, W1, as1, ad1);

    // join
    cudaStreamWaitEvent(0, ev1, 0);

    // ---- layer 1 aggregation + fused layer-2 GEMM ----
    edge1_fused<<<(N_NODES + 7) / 8, 256>>>(b1, W2, as2, ad2);

    // ---- layer 2 ----
    edge_csr2<<<(N_NODES * 32 + 255) / 256, 256>>>(out, b2);

    cudaEventDestroy(ev0);
    cudaEventDestroy(ev1);
    cudaStreamDestroy(s1);
}

// round 15
// speedup vs baseline: 1.1814x; 1.0990x over previous
#include <cuda_runtime.h>
#include <cuda_fp16.h>

#define N_NODES 100000
#define N_EDGES 1600000
#define TOT_E   (N_EDGES + N_NODES)   // edges + self loops
#define F_IN    128
#define HEADS   8
#define HID     8
#define HC      64
#define NCLS    40
#define NEG_SLOPE 0.2f
#define NB_SCAN 98                     // ceil((N_NODES+1)/1024)

typedef unsigned long long u64;

// ---------------- scratch (static device globals, zero-initialized) ---------
__device__ __align__(16) __half2 g_h1h[N_NODES * 32];   // layer1 features, fp16 pairs
__device__ __align__(8) __half2 g_e1[N_NODES * HEADS];  // (exp(as1), exp(.2 as1))
__device__ float g_ad1[N_NODES * HEADS];
__device__ __align__(16) __half2 g_h2h[N_NODES * 20];   // layer2 features, fp16 pairs
__device__ __half2 g_e2[N_NODES];
__device__ float g_ad2[N_NODES];
__device__ int  g_csr_src[TOT_E];
__device__ __align__(8) int g_rank[TOT_E];
__device__ int  g_deg[N_NODES + 1];     // self-cleaning (zeroed in fixup)
__device__ int  g_off[N_NODES + 1];
__device__ int  g_bsum[NB_SCAN];
__device__ int  g_is64;

// ---------------- packed f32x2 helpers (gemm1 only) --------------------------
__device__ __forceinline__ u64 pack2(float x, float y) {
    u64 r; asm("mov.b64 %0, {%1, %2};" : "=l"(r) : "f"(x), "f"(y)); return r;
}
__device__ __forceinline__ void fma2(u64& a, u64 b, u64 c) {
    asm("fma.rn.f32x2 %0, %1, %2, %0;" : "+l"(a) : "l"(b), "l"(c));
}
__device__ __forceinline__ float2 unpack2(u64 a) {
    float2 f; asm("mov.b64 {%0, %1}, %2;" : "=f"(f.x), "=f"(f.y) : "l"(a)); return f;
}

// ---------------- hist (probe + histogram + rank capture), 2 edges/thread ----
__global__ void hist_dst(const void* __restrict__ ei) {
    __shared__ int s_is64;
    int tid = threadIdx.x;
    if (tid < 32) {
        const long long* p = (const long long*)ei;
        int bad = 0;
#pragma unroll
        for (int k = 0; k < 8; k++) {
            long long v = p[tid * 8 + k];
            if (v < 0 || v >= (long long)N_NODES) bad = 1;
        }
        unsigned m = __ballot_sync(0xffffffffu, bad);
        if (tid == 0) {
            s_is64 = (m == 0u);
            if (blockIdx.x == 0) g_is64 = s_is64;
        }
    }
    __syncthreads();
    unsigned e = (blockIdx.x * 256u + tid) * 2u;
    if (e >= (unsigned)TOT_E) return;
    int d0, d1;
    if (e < (unsigned)N_EDGES) {
        if (s_is64) {
            longlong2 v = *(const longlong2*)((const long long*)ei + N_EDGES + e);
            d0 = (int)v.x; d1 = (int)v.y;
        } else {
            int2 v = *(const int2*)((const int*)ei + N_EDGES + e);
            d0 = v.x; d1 = v.y;
        }
    } else {
        d0 = (int)(e - (unsigned)N_EDGES);
        d1 = d0 + 1;
    }
    int r0 = atomicAdd(&g_deg[d0], 1);
    int r1 = atomicAdd(&g_deg[d1], 1);
    *(int2*)(g_rank + e) = make_int2(r0, r1);
}

__global__ void __launch_bounds__(1024) scan_blocks() {
    __shared__ int sh[1024];
    int t = threadIdx.x;
    unsigned i = blockIdx.x * 1024u + t;
    int v = (i <= N_NODES) ? g_deg[i] : 0;
    sh[t] = v; __syncthreads();
#pragma unroll
    for (int off = 1; off < 1024; off <<= 1) {
        int add = (t >= off) ? sh[t - off] : 0;
        __syncthreads();
        sh[t] += add;
        __syncthreads();
    }
    if (i <= N_NODES) g_off[i] = sh[t] - v;
    if (t == 1023) g_bsum[blockIdx.x] = sh[t];
}

__global__ void __launch_bounds__(256) fixup_offsets() {
    __shared__ int sb[128];
    int t = threadIdx.x;
    if (t < 128) sb[t] = (t < NB_SCAN) ? g_bsum[t] : 0;
    __syncthreads();
#pragma unroll
    for (int off = 1; off < 128; off <<= 1) {
        int add = (t < 128 && t >= off) ? sb[t - off] : 0;
        __syncthreads();
        if (t < 128) sb[t] += add;
        __syncthreads();
    }
    unsigned i = blockIdx.x * 256u + t;
    if (i > N_NODES) return;
    unsigned b = i >> 10;
    int pre = (b == 0) ? 0 : sb[b - 1];       // exclusive
    g_off[i] = g_off[i] + pre;
    g_deg[i] = 0;                             // self-clean for next call
}

// ---------------- scatter (atomic-free), 2 edges/thread ----------------------
__global__ void scatter_csr(const void* __restrict__ ei) {
    unsigned e = (blockIdx.x * 256u + threadIdx.x) * 2u;
    if (e >= (unsigned)TOT_E) return;
    int s0, s1, d0, d1;
    if (e < (unsigned)N_EDGES) {
        if (g_is64) {
            longlong2 vs = *(const longlong2*)((const long long*)ei + e);
            longlong2 vd = *(const longlong2*)((const long long*)ei + N_EDGES + e);
            s0 = (int)vs.x; s1 = (int)vs.y; d0 = (int)vd.x; d1 = (int)vd.y;
        } else {
            int2 vs = *(const int2*)((const int*)ei + e);
            int2 vd = *(const int2*)((const int*)ei + N_EDGES + e);
            s0 = vs.x; s1 = vs.y; d0 = vd.x; d1 = vd.y;
        }
    } else {
        s0 = d0 = (int)(e - (unsigned)N_EDGES);
        s1 = d1 = s0 + 1;
    }
    int2 r = *(const int2*)(g_rank + e);
    g_csr_src[g_off[d0] + r.x] = s0;
    g_csr_src[g_off[d1] + r.y] = s1;
}

// ---------------- layer 1 GEMM: 8 nodes/warp, f32x2 accumulation -------------
__global__ void __launch_bounds__(256) gemm1(const float* __restrict__ x,
                                             const float* __restrict__ W,
                                             const float* __restrict__ asrc,
                                             const float* __restrict__ adst) {
    __shared__ float Ws[F_IN * HC];           // 32 KB
    __shared__ float xs[8][F_IN * 8];         // 32 KB: [warp][k*8 + node]
    __shared__ float as_s[HC], ad_s[HC];

    int tid = threadIdx.x;
    for (int i = tid; i < F_IN * HC; i += 256) Ws[i] = W[i];
    if (tid < HC) { as_s[tid] = asrc[tid]; ad_s[tid] = adst[tid]; }

    int warp = tid >> 5, lane = tid & 31;
    int n0 = blockIdx.x * 64 + warp * 8;

#pragma unroll
    for (int u = 0; u < 8; u++) {
        int n = n0 + u; if (n >= N_NODES) n = N_NODES - 1;
        const float* xr = x + (size_t)n * F_IN;
#pragma unroll
        for (int c = 0; c < 4; c++) {
            int k = lane + c * 32;
            xs[warp][k * 8 + u] = xr[k];
        }
    }
    __syncthreads();

    const float2* W2p = (const float2*)Ws;
    u64 acc[8];
#pragma unroll
    for (int u = 0; u < 8; u++) acc[u] = 0;

#pragma unroll 4
    for (int k = 0; k < F_IN; k++) {
        float4 xa = *(const float4*)&xs[warp][k * 8];
        float4 xb = *(const float4*)&xs[warp][k * 8 + 4];
        float2 wv = W2p[k * 32 + lane];
        u64 wp = pack2(wv.x, wv.y);
        fma2(acc[0], pack2(xa.x, xa.x), wp);
        fma2(acc[1], pack2(xa.y, xa.y), wp);
        fma2(acc[2], pack2(xa.z, xa.z), wp);
        fma2(acc[3], pack2(xa.w, xa.w), wp);
        fma2(acc[4], pack2(xb.x, xb.x), wp);
        fma2(acc[5], pack2(xb.y, xb.y), wp);
        fma2(acc[6], pack2(xb.z, xb.z), wp);
        fma2(acc[7], pack2(xb.w, xb.w), wp);
    }

    int j0 = lane * 2;
    float asx = as_s[j0], asy = as_s[j0 + 1];
    float adx = ad_s[j0], ady = ad_s[j0 + 1];

#pragma unroll
    for (int u = 0; u < 8; u++) {
        int n = n0 + u;
        float2 f = unpack2(acc[u]);
        float A0 = f.x, A1 = f.y;
        float ps = A0 * asx + A1 * asy;
        float pd = A0 * adx + A1 * ady;
        ps += __shfl_xor_sync(0xffffffffu, ps, 1);
        ps += __shfl_xor_sync(0xffffffffu, ps, 2);
        pd += __shfl_xor_sync(0xffffffffu, pd, 1);
        pd += __shfl_xor_sync(0xffffffffu, pd, 2);
        if (n < N_NODES) {
            g_h1h[n * 32 + lane] = __floats2half2_rn(A0, A1);
            if ((lane & 3) == 0) {
                int hh = lane >> 2;
                g_e1[n * HEADS + hh] = __floats2half2_rn(__expf(ps), __expf(0.2f * ps));
                g_ad1[n * HEADS + hh] = pd;
            }
        }
    }
}

// ---------------- edge step helpers ------------------------------------------
__device__ __forceinline__ void edge1_step(int S, int q, float epd, float emd,
    float& den, float& a0, float& a1, float& a2, float& a3,
    float& a4, float& a5, float& a6, float& a7) {
    __half2 es = g_e1[S * 8 + q];
    uint4 h = *(const uint4*)(g_h1h + S * 32 + q * 4);
    float2 ef = __half22float2(es);
    float pe = ef.x * epd;
    float e = pe > 1.f ? pe : ef.y * emd;
    den += e;
    float2 v0 = __half22float2(*(__half2*)&h.x);
    float2 v1 = __half22float2(*(__half2*)&h.y);
    float2 v2 = __half22float2(*(__half2*)&h.z);
    float2 v3 = __half22float2(*(__half2*)&h.w);
    a0 += e * v0.x; a1 += e * v0.y; a2 += e * v1.x; a3 += e * v1.y;
    a4 += e * v2.x; a5 += e * v2.y; a6 += e * v3.x; a7 += e * v3.y;
}

__device__ __forceinline__ void edge2_step(int S, int ti, float epd, float emd,
    float& den, float& a0, float& a1, float& a2, float& a3,
    float& a4, float& a5, float& a6, float& a7) {
    __half2 es = g_e2[S];
    uint4 h = *(const uint4*)((const uint4*)g_h2h + S * 5 + ti);
    float2 ef = __half22float2(es);
    float pe = ef.x * epd;
    float e = pe > 1.f ? pe : ef.y * emd;
    den += e;
    float2 v0 = __half22float2(*(__half2*)&h.x);
    float2 v1 = __half22float2(*(__half2*)&h.y);
    float2 v2 = __half22float2(*(__half2*)&h.z);
    float2 v3 = __half22float2(*(__half2*)&h.w);
    a0 += e * v0.x; a1 += e * v0.y; a2 += e * v1.x; a3 += e * v1.y;
    a4 += e * v2.x; a5 += e * v2.y; a6 += e * v3.x; a7 += e * v3.y;
}

// ---------------- layer 1 aggregation: 2 nodes/warp interleaved + fused gemm2
__global__ void __launch_bounds__(256) edge1_fused(const float* __restrict__ b1,
                                                   const float* __restrict__ W2,
                                                   const float* __restrict__ as2v,
                                                   const float* __restrict__ ad2v) {
    __shared__ float Ws2[HC * NCLS];          // 10 KB
    __shared__ float a2s[NCLS], a2d[NCLS];
    __shared__ __align__(16) float hs[16][HC];

    int tid = threadIdx.x;
    for (int i = tid; i < HC * NCLS; i += 256) Ws2[i] = W2[i];
    if (tid < NCLS) { a2s[tid] = as2v[tid]; a2d[tid] = ad2v[tid]; }
    __syncthreads();

    int warp = tid >> 5, lane = tid & 31;
    int nA = blockIdx.x * 16 + warp * 2;      // N_NODES % 16 == 0
    int nB = nA + 1;
    int q = lane & 7;                          // head
    int p = lane >> 3;                         // edge slot 0..3

    float adA = g_ad1[nA * 8 + q];
    float adB = g_ad1[nB * 8 + q];
    float epdA = __expf(adA), emdA = __expf(0.2f * adA);
    float epdB = __expf(adB), emdB = __expf(0.2f * adB);
    float dA = 0.f, A0 = 0.f, A1 = 0.f, A2 = 0.f, A3 = 0.f, A4 = 0.f, A5 = 0.f, A6 = 0.f, A7 = 0.f;
    float dB = 0.f, B0 = 0.f, B1 = 0.f, B2 = 0.f, B3 = 0.f, B4 = 0.f, B5 = 0.f, B6 = 0.f, B7 = 0.f;

    int kA = g_off[nA] + p, endA = g_off[nA + 1];
    int kB = g_off[nB] + p, endB = g_off[nB + 1];

    // interleaved main loop: 2 edges per node per iteration (4 chains in flight)
    while (kA + 4 < endA && kB + 4 < endB) {
        int sA0 = g_csr_src[kA];
        int sA1 = g_csr_src[kA + 4];
        int sB0 = g_csr_src[kB];
        int sB1 = g_csr_src[kB + 4];
        edge1_step(sA0, q, epdA, emdA, dA, A0, A1, A2, A3, A4, A5, A6, A7);
        edge1_step(sB0, q, epdB, emdB, dB, B0, B1, B2, B3, B4, B5, B6, B7);
        edge1_step(sA1, q, epdA, emdA, dA, A0, A1, A2, A3, A4, A5, A6, A7);
        edge1_step(sB1, q, epdB, emdB, dB, B0, B1, B2, B3, B4, B5, B6, B7);
        kA += 8; kB += 8;
    }
    // drains
    for (; kA + 4 < endA; kA += 8) {
        int s0 = g_csr_src[kA], s1 = g_csr_src[kA + 4];
        edge1_step(s0, q, epdA, emdA, dA, A0, A1, A2, A3, A4, A5, A6, A7);
        edge1_step(s1, q, epdA, emdA, dA, A0, A1, A2, A3, A4, A5, A6, A7);
    }
    for (; kA < endA; kA += 4)
        edge1_step(g_csr_src[kA], q, epdA, emdA, dA, A0, A1, A2, A3, A4, A5, A6, A7);
    for (; kB + 4 < endB; kB += 8) {
        int s0 = g_csr_src[kB], s1 = g_csr_src[kB + 4];
        edge1_step(s0, q, epdB, emdB, dB, B0, B1, B2, B3, B4, B5, B6, B7);
        edge1_step(s1, q, epdB, emdB, dB, B0, B1, B2, B3, B4, B5, B6, B7);
    }
    for (; kB < endB; kB += 4)
        edge1_step(g_csr_src[kB], q, epdB, emdB, dB, B0, B1, B2, B3, B4, B5, B6, B7);

#define RED(X) X += __shfl_xor_sync(0xffffffffu, X, 8); X += __shfl_xor_sync(0xffffffffu, X, 16);
    RED(dA) RED(A0) RED(A1) RED(A2) RED(A3) RED(A4) RED(A5) RED(A6) RED(A7)
    RED(dB) RED(B0) RED(B1) RED(B2) RED(B3) RED(B4) RED(B5) RED(B6) RED(B7)
#undef RED

    if (p == 0) {
        int c0 = q * 8;
        float4 ba = *(const float4*)(b1 + c0);
        float4 bb = *(const float4*)(b1 + c0 + 4);
        float invA = 1.f / (dA + 1e-16f);
        float invB = 1.f / (dB + 1e-16f);
        int rA = warp * 2, rB = rA + 1;
        hs[rA][c0]     = fmaxf(A0 * invA + ba.x, 0.f);
        hs[rA][c0 + 1] = fmaxf(A1 * invA + ba.y, 0.f);
        hs[rA][c0 + 2] = fmaxf(A2 * invA + ba.z, 0.f);
        hs[rA][c0 + 3] = fmaxf(A3 * invA + ba.w, 0.f);
        hs[rA][c0 + 4] = fmaxf(A4 * invA + bb.x, 0.f);
        hs[rA][c0 + 5] = fmaxf(A5 * invA + bb.y, 0.f);
        hs[rA][c0 + 6] = fmaxf(A6 * invA + bb.z, 0.f);
        hs[rA][c0 + 7] = fmaxf(A7 * invA + bb.w, 0.f);
        hs[rB][c0]     = fmaxf(B0 * invB + ba.x, 0.f);
        hs[rB][c0 + 1] = fmaxf(B1 * invB + ba.y, 0.f);
        hs[rB][c0 + 2] = fmaxf(B2 * invB + ba.z, 0.f);
        hs[rB][c0 + 3] = fmaxf(B3 * invB + ba.w, 0.f);
        hs[rB][c0 + 4] = fmaxf(B4 * invB + bb.x, 0.f);
        hs[rB][c0 + 5] = fmaxf(B5 * invB + bb.y, 0.f);
        hs[rB][c0 + 6] = fmaxf(B6 * invB + bb.z, 0.f);
        hs[rB][c0 + 7] = fmaxf(B7 * invB + bb.w, 0.f);
    }
    __syncwarp();

    // ---- fused layer-2 GEMM for both nodes; W2 shared-loads amortized ----
    float acc0A = 0.f, acc1A = 0.f, acc0B = 0.f, acc1B = 0.f;
    int l8 = 32 + (lane & 7);
    int rA = warp * 2, rB = rA + 1;
#pragma unroll
    for (int w = 0; w < HC; w += 4) {
        float4 hA = *(const float4*)&hs[rA][w];
        float4 hB = *(const float4*)&hs[rB][w];
        float w0l = Ws2[(w + 0) * NCLS + lane], w1l = Ws2[(w + 1) * NCLS + lane];
        float w2l = Ws2[(w + 2) * NCLS + lane], w3l = Ws2[(w + 3) * NCLS + lane];
        float w0h = Ws2[(w + 0) * NCLS + l8], w1h = Ws2[(w + 1) * NCLS + l8];
        float w2h = Ws2[(w + 2) * NCLS + l8], w3h = Ws2[(w + 3) * NCLS + l8];
        acc0A += hA.x * w0l + hA.y * w1l + hA.z * w2l + hA.w * w3l;
        acc0B += hB.x * w0l + hB.y * w1l + hB.z * w2l + hB.w * w3l;
        acc1A += hA.x * w0h + hA.y * w1h + hA.z * w2h + hA.w * w3h;
        acc1B += hB.x * w0h + hB.y * w1h + hB.z * w2h + hB.w * w3h;
    }

    __half* h2p = (__half*)g_h2h;
    h2p[nA * NCLS + lane] = __float2half_rn(acc0A);
    h2p[nB * NCLS + lane] = __float2half_rn(acc0B);
    if (lane < 8) {
        h2p[nA * NCLS + 32 + lane] = __float2half_rn(acc1A);
        h2p[nB * NCLS + 32 + lane] = __float2half_rn(acc1B);
    }

    float psA = acc0A * a2s[lane] + (lane < 8 ? acc1A * a2s[32 + lane] : 0.f);
    float pdA = acc0A * a2d[lane] + (lane < 8 ? acc1A * a2d[32 + lane] : 0.f);
    float psB = acc0B * a2s[lane] + (lane < 8 ? acc1B * a2s[32 + lane] : 0.f);
    float pdB = acc0B * a2d[lane] + (lane < 8 ? acc1B * a2d[32 + lane] : 0.f);
#pragma unroll
    for (int o = 16; o; o >>= 1) {
        psA += __shfl_xor_sync(0xffffffffu, psA, o);
        pdA += __shfl_xor_sync(0xffffffffu, pdA, o);
        psB += __shfl_xor_sync(0xffffffffu, psB, o);
        pdB += __shfl_xor_sync(0xffffffffu, pdB, o);
    }
    if (lane == 0) {
        g_e2[nA] = __floats2half2_rn(__expf(psA), __expf(0.2f * psA));
        g_ad2[nA] = pdA;
        g_e2[nB] = __floats2half2_rn(__expf(psB), __expf(0.2f * psB));
        g_ad2[nB] = pdB;
    }
}

// ---------------- layer 2 CSR aggregation: 2 nodes/warp interleaved ----------
// 6 groups of 5 lanes; lane t owns classes [8t,8t+8).
__global__ void __launch_bounds__(256) edge_csr2(float* __restrict__ out,
                                                 const float* __restrict__ b2) {
    int warp = (blockIdx.x * 256 + threadIdx.x) >> 5;
    int lane = threadIdx.x & 31;
    int nA = warp * 2;                         // grid covers N_NODES/2 warps
    int nB = nA + 1;
    if (nA >= N_NODES) return;
    int g = lane / 5;
    int t = lane - g * 5;
    bool live = g < 6;
    int ti = live ? t : 0;

    float adA = g_ad2[nA], adB = g_ad2[nB];
    float epdA = __expf(adA), emdA = __expf(0.2f * adA);
    float epdB = __expf(adB), emdB = __expf(0.2f * adB);
    float dA = 0.f, A0 = 0.f, A1 = 0.f, A2 = 0.f, A3 = 0.f, A4 = 0.f, A5 = 0.f, A6 = 0.f, A7 = 0.f;
    float dB = 0.f, B0 = 0.f, B1 = 0.f, B2 = 0.f, B3 = 0.f, B4 = 0.f, B5 = 0.f, B6 = 0.f, B7 = 0.f;

    int kA = g_off[nA] + g, endA = g_off[nA + 1];
    int kB = g_off[nB] + g, endB = g_off[nB + 1];
    if (!live) { kA = endA = 0; kB = endB = 0; }

    while (kA < endA && kB < endB) {
        int sA = g_csr_src[kA];
        int sB = g_csr_src[kB];
        edge2_step(sA, ti, epdA, emdA, dA, A0, A1, A2, A3, A4, A5, A6, A7);
        edge2_step(sB, ti, epdB, emdB, dB, B0, B1, B2, B3, B4, B5, B6, B7);
        kA += 6; kB += 6;
    }
    for (; kA + 6 < endA; kA += 12) {
        int s0 = g_csr_src[kA], s1 = g_csr_src[kA + 6];
        edge2_step(s0, ti, epdA, emdA, dA, A0, A1, A2, A3, A4, A5, A6, A7);
        edge2_step(s1, ti, epdA, emdA, dA, A0, A1, A2, A3, A4, A5, A6, A7);
    }
    for (; kA < endA; kA += 6)
        edge2_step(g_csr_src[kA], ti, epdA, emdA, dA, A0, A1, A2, A3, A4, A5, A6, A7);
    for (; kB + 6 < endB; kB += 12) {
        int s0 = g_csr_src[kB], s1 = g_csr_src[kB + 6];
        edge2_step(s0, ti, epdB, emdB, dB, B0, B1, B2, B3, B4, B5, B6, B7);
        edge2_step(s1, ti, epdB, emdB, dB, B0, B1, B2, B3, B4, B5, B6, B7);
    }
    for (; kB < endB; kB += 6)
        edge2_step(g_csr_src[kB], ti, epdB, emdB, dB, B0, B1, B2, B3, B4, B5, B6, B7);

#define RED(X)                                                                   \
    {                                                                            \
        float w_ = __shfl_sync(0xffffffffu, X, (lane + 15) & 31); X += w_;       \
        float u_ = __shfl_sync(0xffffffffu, X, (lane + 5) & 31);                 \
        float v_ = __shfl_sync(0xffffffffu, X, (lane + 10) & 31);                \
        X += u_ + v_;                                                            \
    }
    RED(dA) RED(A0) RED(A1) RED(A2) RED(A3) RED(A4) RED(A5) RED(A6) RED(A7)
    RED(dB) RED(B0) RED(B1) RED(B2) RED(B3) RED(B4) RED(B5) RED(B6) RED(B7)
#undef RED

    if (lane < 5) {
        int c0 = lane * 8;
        float4 ba = *(const float4*)(b2 + c0);
        float4 bb = *(const float4*)(b2 + c0 + 4);
        float invA = 1.f / (dA + 1e-16f);
        float invB = 1.f / (dB + 1e-16f);
        float4 r0, r1;
        r0.x = A0 * invA + ba.x; r0.y = A1 * invA + ba.y;
        r0.z = A2 * invA + ba.z; r0.w = A3 * invA + ba.w;
        r1.x = A4 * invA + bb.x; r1.y = A5 * invA + bb.y;
        r1.z = A6 * invA + bb.z; r1.w = A7 * invA + bb.w;
        *(float4*)(out + nA * NCLS + c0)     = r0;
        *(float4*)(out + nA * NCLS + c0 + 4) = r1;
        r0.x = B0 * invB + ba.x; r0.y = B1 * invB + ba.y;
        r0.z = B2 * invB + ba.z; r0.w = B3 * invB + ba.w;
        r1.x = B4 * invB + bb.x; r1.y = B5 * invB + bb.y;
        r1.z = B6 * invB + bb.z; r1.w = B7 * invB + bb.w;
        *(float4*)(out + nB * NCLS + c0)     = r0;
        *(float4*)(out + nB * NCLS + c0 + 4) = r1;
    }
}

// ---------------- launch -----------------------------------------------------
extern "C" void kernel_launch(void* const* d_in, const int* in_sizes, int n_in,
                              void* d_out, int out_size) {
    const float* x   = (const float*)d_in[0];
    const void*  ei  = d_in[1];
    const float* W1  = (const float*)d_in[2];
    const float* as1 = (const float*)d_in[3];
    const float* ad1 = (const float*)d_in[4];
    const float* b1  = (const float*)d_in[5];
    const float* W2  = (const float*)d_in[6];
    const float* as2 = (const float*)d_in[7];
    const float* ad2 = (const float*)d_in[8];
    const float* b2  = (const float*)d_in[9];
    float*       out = (float*)d_out;

    // fork: CSR build on side stream, gemm1 concurrently on main stream
    cudaStream_t s1;
    cudaStreamCreateWithFlags(&s1, cudaStreamNonBlocking);
    cudaEvent_t ev0, ev1;
    cudaEventCreateWithFlags(&ev0, cudaEventDisableTiming);
    cudaEventCreateWithFlags(&ev1, cudaEventDisableTiming);

    cudaEventRecord(ev0, 0);
    cudaStreamWaitEvent(s1, ev0, 0);

    // ---- CSR build (side stream) ----
    hist_dst<<<((unsigned)TOT_E / 2 + 255) / 256, 256, 0, s1>>>(ei);
    scan_blocks<<<NB_SCAN, 1024, 0, s1>>>();
    fixup_offsets<<<(N_NODES + 256) / 256, 256, 0, s1>>>();
    scatter_csr<<<((unsigned)TOT_E / 2 + 255) / 256, 256, 0, s1>>>(ei);
    cudaEventRecord(ev1, s1);

    // ---- layer 1 GEMM (main stream, overlapped) ----
    gemm1<<<(N_NODES + 63) / 64, 256>>>(x, W1, as1, ad1);

    // join
    cudaStreamWaitEvent(0, ev1, 0);

    // ---- layer 1 aggregation (2 nodes/warp) + fused layer-2 GEMM ----
    edge1_fused<<<N_NODES / 16, 256>>>(b1, W2, as2, ad2);

    // ---- layer 2 (2 nodes/warp) ----
    edge_csr2<<<N_NODES / 16, 256>>>(out, b2);

    cudaEventDestroy(ev0);
    cudaEventDestroy(ev1);
    cudaStreamDestroy(s1);
}

// round 16
// speedup vs baseline: 1.3749x; 1.1638x over previous
#include <cuda_runtime.h>
#include <cuda_fp16.h>

#define N_NODES 100000
#define N_EDGES 1600000
#define TOT_E   (N_EDGES + N_NODES)   // edges + self loops
#define F_IN    128
#define HEADS   8
#define HID     8
#define HC      64
#define NCLS    40
#define NEG_SLOPE 0.2f
#define NB_SCAN 98                     // ceil((N_NODES+1)/1024)

typedef unsigned long long u64;

// ---------------- scratch (static device globals, zero-initialized) ---------
__device__ __align__(16) __half2 g_h1h[N_NODES * 32];   // layer1 features, fp16 pairs
__device__ __align__(8) __half2 g_e1[N_NODES * HEADS];  // (exp(as1), exp(.2 as1))
__device__ float g_ad1[N_NODES * HEADS];
__device__ __align__(16) __half2 g_h2h[N_NODES * 20];   // layer2 features, fp16 pairs
__device__ __half2 g_e2[N_NODES];
__device__ float g_ad2[N_NODES];
__device__ int  g_csr_src[TOT_E];
__device__ __align__(8) int g_rank[TOT_E];
__device__ int  g_deg[N_NODES + 1];     // self-cleaning (zeroed in fixup)
__device__ int  g_off[N_NODES + 1];
__device__ int  g_bsum[NB_SCAN];
__device__ int  g_is64;

// ---------------- packed f32x2 helpers (gemm1 only) --------------------------
__device__ __forceinline__ u64 pack2(float x, float y) {
    u64 r; asm("mov.b64 %0, {%1, %2};" : "=l"(r) : "f"(x), "f"(y)); return r;
}
__device__ __forceinline__ void fma2(u64& a, u64 b, u64 c) {
    asm("fma.rn.f32x2 %0, %1, %2, %0;" : "+l"(a) : "l"(b), "l"(c));
}
__device__ __forceinline__ float2 unpack2(u64 a) {
    float2 f; asm("mov.b64 {%0, %1}, %2;" : "=f"(f.x), "=f"(f.y) : "l"(a)); return f;
}

// ---------------- hist (probe + histogram + rank capture), 2 edges/thread ----
__global__ void hist_dst(const void* __restrict__ ei) {
    __shared__ int s_is64;
    int tid = threadIdx.x;
    if (tid < 32) {
        const long long* p = (const long long*)ei;
        int bad = 0;
#pragma unroll
        for (int k = 0; k < 8; k++) {
            long long v = p[tid * 8 + k];
            if (v < 0 || v >= (long long)N_NODES) bad = 1;
        }
        unsigned m = __ballot_sync(0xffffffffu, bad);
        if (tid == 0) {
            s_is64 = (m == 0u);
            if (blockIdx.x == 0) g_is64 = s_is64;
        }
    }
    __syncthreads();
    unsigned e = (blockIdx.x * 256u + tid) * 2u;
    if (e >= (unsigned)TOT_E) return;
    int d0, d1;
    if (e < (unsigned)N_EDGES) {
        if (s_is64) {
            longlong2 v = *(const longlong2*)((const long long*)ei + N_EDGES + e);
            d0 = (int)v.x; d1 = (int)v.y;
        } else {
            int2 v = *(const int2*)((const int*)ei + N_EDGES + e);
            d0 = v.x; d1 = v.y;
        }
    } else {
        d0 = (int)(e - (unsigned)N_EDGES);
        d1 = d0 + 1;
    }
    int r0 = atomicAdd(&g_deg[d0], 1);
    int r1 = atomicAdd(&g_deg[d1], 1);
    *(int2*)(g_rank + e) = make_int2(r0, r1);
}

__global__ void __launch_bounds__(1024) scan_blocks() {
    __shared__ int sh[1024];
    int t = threadIdx.x;
    unsigned i = blockIdx.x * 1024u + t;
    int v = (i <= N_NODES) ? g_deg[i] : 0;
    sh[t] = v; __syncthreads();
#pragma unroll
    for (int off = 1; off < 1024; off <<= 1) {
        int add = (t >= off) ? sh[t - off] : 0;
        __syncthreads();
        sh[t] += add;
        __syncthreads();
    }
    if (i <= N_NODES) g_off[i] = sh[t] - v;
    if (t == 1023) g_bsum[blockIdx.x] = sh[t];
}

__global__ void __launch_bounds__(256) fixup_offsets() {
    __shared__ int sb[128];
    int t = threadIdx.x;
    if (t < 128) sb[t] = (t < NB_SCAN) ? g_bsum[t] : 0;
    __syncthreads();
#pragma unroll
    for (int off = 1; off < 128; off <<= 1) {
        int add = (t < 128 && t >= off) ? sb[t - off] : 0;
        __syncthreads();
        if (t < 128) sb[t] += add;
        __syncthreads();
    }
    unsigned i = blockIdx.x * 256u + t;
    if (i > N_NODES) return;
    unsigned b = i >> 10;
    int pre = (b == 0) ? 0 : sb[b - 1];       // exclusive
    g_off[i] = g_off[i] + pre;
    g_deg[i] = 0;                             // self-clean for next call
}

// ---------------- scatter (atomic-free), 2 edges/thread ----------------------
__global__ void scatter_csr(const void* __restrict__ ei) {
    unsigned e = (blockIdx.x * 256u + threadIdx.x) * 2u;
    if (e >= (unsigned)TOT_E) return;
    int s0, s1, d0, d1;
    if (e < (unsigned)N_EDGES) {
        if (g_is64) {
            longlong2 vs = *(const longlong2*)((const long long*)ei + e);
            longlong2 vd = *(const longlong2*)((const long long*)ei + N_EDGES + e);
            s0 = (int)vs.x; s1 = (int)vs.y; d0 = (int)vd.x; d1 = (int)vd.y;
        } else {
            int2 vs = *(const int2*)((const int*)ei + e);
            int2 vd = *(const int2*)((const int*)ei + N_EDGES + e);
            s0 = vs.x; s1 = vs.y; d0 = vd.x; d1 = vd.y;
        }
    } else {
        s0 = d0 = (int)(e - (unsigned)N_EDGES);
        s1 = d1 = s0 + 1;
    }
    int2 r = *(const int2*)(g_rank + e);
    g_csr_src[g_off[d0] + r.x] = s0;
    g_csr_src[g_off[d1] + r.y] = s1;
}

// ---------------- layer 1 GEMM: 8 nodes/warp, f32x2 accumulation -------------
__global__ void __launch_bounds__(256) gemm1(const float* __restrict__ x,
                                             const float* __restrict__ W,
                                             const float* __restrict__ asrc,
                                             const float* __restrict__ adst) {
    __shared__ float Ws[F_IN * HC];           // 32 KB
    __shared__ float xs[8][F_IN * 8];         // 32 KB: [warp][k*8 + node]
    __shared__ float as_s[HC], ad_s[HC];

    int tid = threadIdx.x;
    for (int i = tid; i < F_IN * HC; i += 256) Ws[i] = W[i];
    if (tid < HC) { as_s[tid] = asrc[tid]; ad_s[tid] = adst[tid]; }

    int warp = tid >> 5, lane = tid & 31;
    int n0 = blockIdx.x * 64 + warp * 8;

#pragma unroll
    for (int u = 0; u < 8; u++) {
        int n = n0 + u; if (n >= N_NODES) n = N_NODES - 1;
        const float* xr = x + (size_t)n * F_IN;
#pragma unroll
        for (int c = 0; c < 4; c++) {
            int k = lane + c * 32;
            xs[warp][k * 8 + u] = xr[k];
        }
    }
    __syncthreads();

    const float2* W2p = (const float2*)Ws;
    u64 acc[8];
#pragma unroll
    for (int u = 0; u < 8; u++) acc[u] = 0;

#pragma unroll 4
    for (int k = 0; k < F_IN; k++) {
        float4 xa = *(const float4*)&xs[warp][k * 8];
        float4 xb = *(const float4*)&xs[warp][k * 8 + 4];
        float2 wv = W2p[k * 32 + lane];
        u64 wp = pack2(wv.x, wv.y);
        fma2(acc[0], pack2(xa.x, xa.x), wp);
        fma2(acc[1], pack2(xa.y, xa.y), wp);
        fma2(acc[2], pack2(xa.z, xa.z), wp);
        fma2(acc[3], pack2(xa.w, xa.w), wp);
        fma2(acc[4], pack2(xb.x, xb.x), wp);
        fma2(acc[5], pack2(xb.y, xb.y), wp);
        fma2(acc[6], pack2(xb.z, xb.z), wp);
        fma2(acc[7], pack2(xb.w, xb.w), wp);
    }

    int j0 = lane * 2;
    float asx = as_s[j0], asy = as_s[j0 + 1];
    float adx = ad_s[j0], ady = ad_s[j0 + 1];

#pragma unroll
    for (int u = 0; u < 8; u++) {
        int n = n0 + u;
        float2 f = unpack2(acc[u]);
        float A0 = f.x, A1 = f.y;
        float ps = A0 * asx + A1 * asy;
        float pd = A0 * adx + A1 * ady;
        ps += __shfl_xor_sync(0xffffffffu, ps, 1);
        ps += __shfl_xor_sync(0xffffffffu, ps, 2);
        pd += __shfl_xor_sync(0xffffffffu, pd, 1);
        pd += __shfl_xor_sync(0xffffffffu, pd, 2);
        if (n < N_NODES) {
            g_h1h[n * 32 + lane] = __floats2half2_rn(A0, A1);
            if ((lane & 3) == 0) {
                int hh = lane >> 2;
                g_e1[n * HEADS + hh] = __floats2half2_rn(__expf(ps), __expf(0.2f * ps));
                g_ad1[n * HEADS + hh] = pd;
            }
        }
    }
}

// ---------------- layer 1 aggregation: group-per-node, no shuffles ----------
// Warp = 4 nodes (8-lane groups). Lane q = head q owns its 8 channels AND its
// head's denominator — zero reduction. Stride-1 csr walk, unroll 4 (4 chains).
__global__ void __launch_bounds__(256) edge1_fused(const float* __restrict__ b1,
                                                   const float* __restrict__ W2,
                                                   const float* __restrict__ as2v,
                                                   const float* __restrict__ ad2v) {
    __shared__ float Ws2[HC * NCLS];          // 10 KB
    __shared__ float a2s[NCLS], a2d[NCLS];
    __shared__ __align__(16) float hs[32][HC]; // 8 KB: 8 warps x 4 nodes

    int tid = threadIdx.x;
    for (int i = tid; i < HC * NCLS; i += 256) Ws2[i] = W2[i];
    if (tid < NCLS) { a2s[tid] = as2v[tid]; a2d[tid] = ad2v[tid]; }
    __syncthreads();

    int warp = tid >> 5, lane = tid & 31;
    int g = lane >> 3;                         // group = node slot 0..3
    int q = lane & 7;                          // head
    int n = blockIdx.x * 32 + warp * 4 + g;    // N_NODES % 32 == 0

    float ad  = g_ad1[n * 8 + q];
    float epd = __expf(ad);
    float emd = __expf(0.2f * ad);
    float den = 0.f;
    float a0 = 0.f, a1 = 0.f, a2 = 0.f, a3 = 0.f,
          a4 = 0.f, a5 = 0.f, a6 = 0.f, a7 = 0.f;

#define STEP1(S)                                                                 \
    {                                                                            \
        __half2 es = g_e1[(S) * 8 + q];                                          \
        uint4 h = *(const uint4*)(g_h1h + (S) * 32 + q * 4);                     \
        float2 ef = __half22float2(es);                                          \
        float pe = ef.x * epd;                                                   \
        float e = pe > 1.f ? pe : ef.y * emd;                                    \
        den += e;                                                                \
        float2 v0 = __half22float2(*(__half2*)&h.x);                             \
        float2 v1 = __half22float2(*(__half2*)&h.y);                             \
        float2 v2 = __half22float2(*(__half2*)&h.z);                             \
        float2 v3 = __half22float2(*(__half2*)&h.w);                             \
        a0 += e * v0.x; a1 += e * v0.y; a2 += e * v1.x; a3 += e * v1.y;          \
        a4 += e * v2.x; a5 += e * v2.y; a6 += e * v3.x; a7 += e * v3.y;          \
    }

    int k = g_off[n], end = g_off[n + 1];
    for (; k + 4 <= end; k += 4) {             // 4 independent chains per lane
        int s0 = g_csr_src[k];
        int s1 = g_csr_src[k + 1];
        int s2 = g_csr_src[k + 2];
        int s3 = g_csr_src[k + 3];
        STEP1(s0) STEP1(s1) STEP1(s2) STEP1(s3)
    }
    for (; k < end; k++) STEP1(g_csr_src[k])
#undef STEP1

    // write activated row (every lane writes its own 8 channels; no reduce)
    int row = warp * 4 + g;
    int c0 = q * 8;
    {
        float4 ba = *(const float4*)(b1 + c0);
        float4 bb = *(const float4*)(b1 + c0 + 4);
        float inv = 1.f / (den + 1e-16f);
        hs[row][c0]     = fmaxf(a0 * inv + ba.x, 0.f);
        hs[row][c0 + 1] = fmaxf(a1 * inv + ba.y, 0.f);
        hs[row][c0 + 2] = fmaxf(a2 * inv + ba.z, 0.f);
        hs[row][c0 + 3] = fmaxf(a3 * inv + ba.w, 0.f);
        hs[row][c0 + 4] = fmaxf(a4 * inv + bb.x, 0.f);
        hs[row][c0 + 5] = fmaxf(a5 * inv + bb.y, 0.f);
        hs[row][c0 + 6] = fmaxf(a6 * inv + bb.z, 0.f);
        hs[row][c0 + 7] = fmaxf(a7 * inv + bb.w, 0.f);
    }
    __syncwarp();

    // ---- fused layer-2 GEMM for 4 nodes; W2 shared-loads amortized x4 ----
    int rbase = warp * 4;
    int nb = blockIdx.x * 32 + warp * 4;
    float acc0[4] = {0.f, 0.f, 0.f, 0.f};
    float acc1[4] = {0.f, 0.f, 0.f, 0.f};
    int l8 = 32 + (lane & 7);
#pragma unroll
    for (int w = 0; w < HC; w += 4) {
        float w0l = Ws2[(w + 0) * NCLS + lane], w1l = Ws2[(w + 1) * NCLS + lane];
        float w2l = Ws2[(w + 2) * NCLS + lane], w3l = Ws2[(w + 3) * NCLS + lane];
        float w0h = Ws2[(w + 0) * NCLS + l8], w1h = Ws2[(w + 1) * NCLS + l8];
        float w2h = Ws2[(w + 2) * NCLS + l8], w3h = Ws2[(w + 3) * NCLS + l8];
#pragma unroll
        for (int j = 0; j < 4; j++) {
            float4 hv = *(const float4*)&hs[rbase + j][w];
            acc0[j] += hv.x * w0l + hv.y * w1l + hv.z * w2l + hv.w * w3l;
            acc1[j] += hv.x * w0h + hv.y * w1h + hv.z * w2h + hv.w * w3h;
        }
    }

    __half* h2p = (__half*)g_h2h;
#pragma unroll
    for (int j = 0; j < 4; j++) {
        int nn = nb + j;
        h2p[nn * NCLS + lane] = __float2half_rn(acc0[j]);
        if (lane < 8) h2p[nn * NCLS + 32 + lane] = __float2half_rn(acc1[j]);
        float ps = acc0[j] * a2s[lane] + (lane < 8 ? acc1[j] * a2s[32 + lane] : 0.f);
        float pd = acc0[j] * a2d[lane] + (lane < 8 ? acc1[j] * a2d[32 + lane] : 0.f);
#pragma unroll
        for (int o = 16; o; o >>= 1) {
            ps += __shfl_xor_sync(0xffffffffu, ps, o);
            pd += __shfl_xor_sync(0xffffffffu, pd, o);
        }
        if (lane == 0) {
            g_e2[nn] = __floats2half2_rn(__expf(ps), __expf(0.2f * ps));
            g_ad2[nn] = pd;
        }
    }
}

// ---------------- layer 2 aggregation: group-per-node, no shuffles ----------
// Warp = 6 nodes (5-lane groups, lanes 30-31 idle). Lane t owns classes
// [8t,8t+8) and a replicated denominator. Stride-1 walk, unroll 4.
__global__ void __launch_bounds__(256) edge_csr2(float* __restrict__ out,
                                                 const float* __restrict__ b2) {
    int warp = (blockIdx.x * 256 + threadIdx.x) >> 5;
    int lane = threadIdx.x & 31;
    int g = lane / 5;
    int t = lane - g * 5;
    int n = warp * 6 + g;
    bool act = (g < 6) && (n < N_NODES);
    int na = act ? n : 0;
    int ti = act ? t : 0;

    float ad  = g_ad2[na];
    float epd = __expf(ad);
    float emd = __expf(0.2f * ad);
    float den = 0.f;
    float a0 = 0.f, a1 = 0.f, a2 = 0.f, a3 = 0.f,
          a4 = 0.f, a5 = 0.f, a6 = 0.f, a7 = 0.f;

#define STEP2(S)                                                                 \
    {                                                                            \
        __half2 es = g_e2[(S)];                                                  \
        uint4 h = *(const uint4*)((const uint4*)g_h2h + (S) * 5 + ti);           \
        float2 ef = __half22float2(es);                                          \
        float pe = ef.x * epd;                                                   \
        float e = pe > 1.f ? pe : ef.y * emd;                                    \
        den += e;                                                                \
        float2 v0 = __half22float2(*(__half2*)&h.x);                             \
        float2 v1 = __half22float2(*(__half2*)&h.y);                             \
        float2 v2 = __half22float2(*(__half2*)&h.z);                             \
        float2 v3 = __half22float2(*(__half2*)&h.w);                             \
        a0 += e * v0.x; a1 += e * v0.y; a2 += e * v1.x; a3 += e * v1.y;          \
        a4 += e * v2.x; a5 += e * v2.y; a6 += e * v3.x; a7 += e * v3.y;          \
    }

    int k = act ? g_off[na] : 0;
    int end = act ? g_off[na + 1] : 0;
    for (; k + 4 <= end; k += 4) {             // 4 independent chains per lane
        int s0 = g_csr_src[k];
        int s1 = g_csr_src[k + 1];
        int s2 = g_csr_src[k + 2];
        int s3 = g_csr_src[k + 3];
        STEP2(s0) STEP2(s1) STEP2(s2) STEP2(s3)
    }
    for (; k < end; k++) STEP2(g_csr_src[k])
#undef STEP2

    if (act) {
        int c0 = t * 8;
        float4 ba = *(const float4*)(b2 + c0);
        float4 bb = *(const float4*)(b2 + c0 + 4);
        float inv = 1.f / (den + 1e-16f);
        float4 r0, r1;
        r0.x = a0 * inv + ba.x; r0.y = a1 * inv + ba.y;
        r0.z = a2 * inv + ba.z; r0.w = a3 * inv + ba.w;
        r1.x = a4 * inv + bb.x; r1.y = a5 * inv + bb.y;
        r1.z = a6 * inv + bb.z; r1.w = a7 * inv + bb.w;
        *(float4*)(out + n * NCLS + c0)     = r0;
        *(float4*)(out + n * NCLS + c0 + 4) = r1;
    }
}

// ---------------- launch -----------------------------------------------------
extern "C" void kernel_launch(void* const* d_in, const int* in_sizes, int n_in,
                              void* d_out, int out_size) {
    const float* x   = (const float*)d_in[0];
    const void*  ei  = d_in[1];
    const float* W1  = (const float*)d_in[2];
    const float* as1 = (const float*)d_in[3];
    const float* ad1 = (const float*)d_in[4];
    const float* b1  = (const float*)d_in[5];
    const float* W2  = (const float*)d_in[6];
    const float* as2 = (const float*)d_in[7];
    const float* ad2 = (const float*)d_in[8];
    const float* b2  = (const float*)d_in[9];
    float*       out = (float*)d_out;

    // fork: CSR build on side stream, gemm1 concurrently on main stream
    cudaStream_t s1;
    cudaStreamCreateWithFlags(&s1, cudaStreamNonBlocking);
    cudaEvent_t ev0, ev1;
    cudaEventCreateWithFlags(&ev0, cudaEventDisableTiming);
    cudaEventCreateWithFlags(&ev1, cudaEventDisableTiming);

    cudaEventRecord(ev0, 0);
    cudaStreamWaitEvent(s1, ev0, 0);

    // ---- CSR build (side stream) ----
    hist_dst<<<((unsigned)TOT_E / 2 + 255) / 256, 256, 0, s1>>>(ei);
    scan_blocks<<<NB_SCAN, 1024, 0, s1>>>();
    fixup_offsets<<<(N_NODES + 256) / 256, 256, 0, s1>>>();
    scatter_csr<<<((unsigned)TOT_E / 2 + 255) / 256, 256, 0, s1>>>(ei);
    cudaEventRecord(ev1, s1);

    // ---- layer 1 GEMM (main stream, overlapped) ----
    gemm1<<<(N_NODES + 63) / 64, 256>>>(x, W1, as1, ad1);

    // join
    cudaStreamWaitEvent(0, ev1, 0);

    // ---- layer 1 aggregation (4 nodes/warp) + fused layer-2 GEMM ----
    edge1_fused<<<N_NODES / 32, 256>>>(b1, W2, as2, ad2);

    // ---- layer 2 (6 nodes/warp) ----
    edge_csr2<<<(N_NODES + 47) / 48, 256>>>(out, b2);

    cudaEventDestroy(ev0);
    cudaEventDestroy(ev1);
    cudaStreamDestroy(s1);
}